// round 3
// baseline (speedup 1.0000x reference)
#include <cuda_runtime.h>
#include <stdint.h>

#define N_POINTS 1200000
#define NFEAT 5
#define GXD 400
#define GYD 400
#define NCELLS (GXD*GYD)          // 160000
#define MAXV 60000
#define MAXP 32
#define OUT_COORD_OFF (MAXV*MAXP*NFEAT)        // 9,600,000
#define OUT_NUM_OFF   (OUT_COORD_OFF + MAXV*3) // 9,780,000
#define NSCB 625                   // 160000 / 256 (exact)

// dynamic (zeroed each run): [0,NCELLS) = per-cell counts, [NCELLS,NCELLS+NSCB) = lookback state
__device__ unsigned g_dyn[NCELLS + NSCB];
__device__ int      g_cellvox[NCELLS];
__device__ int      g_ptcell[N_POINTS];
__device__ int      g_totvox;
// slot[cell][rank] = two float4: {x,y,z,idx_bits},{f3,f4,-,-}  (32B, one sector)
__device__ float4   g_slot[(size_t)NCELLS * MAXP * 2];

// ---------------- assign: point -> cell, atomic rank, stage full point ----------------
__global__ void k_assign(const float* __restrict__ pts) {
    int i = blockIdx.x * blockDim.x + threadIdx.x;
    if (i >= N_POINTS) return;
    const float* p = pts + (size_t)i * NFEAT;
    float x = p[0], y = p[1], z = p[2], f3 = p[3], f4 = p[4];
    // exact: (v+50)*4 == (v-(-50))/0.25 ; (v+5)*0.125 == (v-(-5))/8
    int cx = (int)floorf((x + 50.0f) * 4.0f);
    int cy = (int)floorf((y + 50.0f) * 4.0f);
    int cz = (int)floorf((z + 5.0f) * 0.125f);
    int cell = -1;
    if (cx >= 0 && cx < GXD && cy >= 0 && cy < GYD && cz == 0) {
        cell = cy * GXD + cx;
        unsigned r = atomicAdd(&g_dyn[cell], 1u);
        if (r < MAXP) {
            size_t s = ((size_t)cell * MAXP + r) * 2;
            g_slot[s]     = make_float4(x, y, z, __int_as_float(i));
            g_slot[s + 1] = make_float4(f3, f4, 0.0f, 0.0f);
        }
    }
    g_ptcell[i] = cell;   // only consumed by the (never-taken) overflow fallback
}

// ---------------- scan: decoupled-lookback exclusive scan of occupancy ----------------
__global__ void k_scan() {
    __shared__ int wsum[8];
    __shared__ unsigned s_prefix;
    unsigned* state = g_dyn + NCELLS;
    int t = threadIdx.x, b = blockIdx.x;
    int lane = t & 31, w = t >> 5;
    int c = b * 256 + t;
    int occ = (g_dyn[c] != 0u) ? 1 : 0;
    // warp inclusive scan
    int x = occ;
    #pragma unroll
    for (int o = 1; o < 32; o <<= 1) {
        int v = __shfl_up_sync(0xffffffffu, x, o);
        if (lane >= o) x += v;
    }
    if (lane == 31) wsum[w] = x;
    __syncthreads();
    if (t < 8) {
        int y = wsum[t];
        #pragma unroll
        for (int o = 1; o < 8; o <<= 1) {
            int v = __shfl_up_sync(0xffu, y, o);
            if (t >= o) y += v;
        }
        wsum[t] = y;   // inclusive warp-sum scan
    }
    __syncthreads();
    int incl = x + (w ? wsum[w - 1] : 0);
    if (t == 0) {
        unsigned aggv = (unsigned)wsum[7];
        if (b == 0) {
            s_prefix = 0;
            __threadfence();
            atomicExch(&state[0], (2u << 30) | aggv);
        } else {
            atomicExch(&state[b], (1u << 30) | aggv);  // publish aggregate
            unsigned run = 0; int j = b - 1;
            for (;;) {
                unsigned s;
                do { s = atomicAdd(&state[j], 0u); } while ((s >> 30) == 0u);
                run += s & 0x3FFFFFFFu;
                if ((s >> 30) == 2u) break;
                j--;
            }
            s_prefix = run;
            __threadfence();
            atomicExch(&state[b], (2u << 30) | (run + aggv));
        }
    }
    __syncthreads();
    int ex = (int)s_prefix + incl - occ;
    g_cellvox[c] = ex;
    if (c == NCELLS - 1) g_totvox = ex + occ;
}

// ---------------- emit: one warp per cell, stable order via index rank; fused tail ----------------
__global__ void k_emit(const float* __restrict__ pts, float* __restrict__ out) {
    int gw   = (blockIdx.x * blockDim.x + threadIdx.x) >> 5;
    int lane = threadIdx.x & 31;
    int w    = (threadIdx.x >> 5) & 7;
    __shared__ float4 sbuf4[8][40];   // 640 B staging per warp
    __shared__ int    sidx[8][32];

    // fused tail: zero voxels with no owner
    if (gw < MAXV && gw >= g_totvox) {
        float4 z = make_float4(0.f, 0.f, 0.f, 0.f);
        float4* dst = (float4*)(out + (size_t)gw * (MAXP * NFEAT));
        for (int j = lane; j < 40; j += 32) dst[j] = z;
        if (lane == 0) {
            float* oc = out + OUT_COORD_OFF + (size_t)gw * 3;
            oc[0] = 0.f; oc[1] = 0.f; oc[2] = 0.f;
            out[OUT_NUM_OFF + gw] = 0.f;
        }
    }

    if (gw >= NCELLS) return;
    int cell = gw;
    int cnt = (int)g_dyn[cell];
    if (cnt == 0) return;
    int v = g_cellvox[cell];
    if (v >= MAXV) return;

    float* sb = (float*)sbuf4[w];
    // zero staging
    #pragma unroll
    for (int j = lane; j < 160; j += 32) sb[j] = 0.0f;
    __syncwarp();

    int n;
    if (cnt <= MAXP) {
        n = cnt;
        float4 a, bb; int pidx;
        size_t base = (size_t)cell * MAXP * 2;
        if (lane < cnt) {
            a  = g_slot[base + (size_t)lane * 2];
            bb = g_slot[base + (size_t)lane * 2 + 1];
            pidx = __float_as_int(a.w);
        } else {
            pidx = 0x7fffffff;
        }
        int rank = 0;
        #pragma unroll
        for (int k = 0; k < 32; k++) {
            int o = __shfl_sync(0xffffffffu, pidx, k);
            rank += (o < pidx) ? 1 : 0;
        }
        if (lane < cnt) {
            float* d = sb + rank * NFEAT;
            d[0] = a.x; d[1] = a.y; d[2] = a.z; d[3] = bb.x; d[4] = bb.y;
        }
        __syncwarp();
    } else {
        // overflow fallback (statistically never): first 32 points in original order
        n = MAXP;
        if (lane == 0) {
            int m = 0;
            for (int j = 0; j < N_POINTS && m < MAXP; j++)
                if (g_ptcell[j] == cell) sidx[w][m++] = j;
        }
        __syncwarp();
        if (lane < MAXP) {
            int idx = sidx[w][lane];
            const float* p = pts + (size_t)idx * NFEAT;
            float* d = sb + lane * NFEAT;
            #pragma unroll
            for (int f = 0; f < NFEAT; f++) d[f] = p[f];
        }
        __syncwarp();
    }

    // coalesced 640B write per voxel
    float4* dst = (float4*)(out + (size_t)v * (MAXP * NFEAT));
    #pragma unroll
    for (int j = lane; j < 40; j += 32) dst[j] = sbuf4[w][j];
    if (lane == 0) {
        int cy = cell / GXD, cx = cell - cy * GXD;
        float* oc = out + OUT_COORD_OFF + (size_t)v * 3;
        oc[0] = 0.0f;           // z
        oc[1] = (float)cy;      // y
        oc[2] = (float)cx;      // x
        out[OUT_NUM_OFF + v] = (float)n;
    }
}

extern "C" void kernel_launch(void* const* d_in, const int* in_sizes, int n_in,
                              void* d_out, int out_size) {
    const float* pts = (const float*)d_in[0];
    float* out = (float*)d_out;
    (void)in_sizes; (void)n_in; (void)out_size;

    void* dynptr = nullptr;
    cudaGetSymbolAddress(&dynptr, g_dyn);
    cudaMemsetAsync(dynptr, 0, sizeof(unsigned) * (NCELLS + NSCB), 0);

    k_assign<<<(N_POINTS + 255) / 256, 256>>>(pts);
    k_scan  <<<NSCB, 256>>>();
    k_emit  <<<(NCELLS * 32 + 255) / 256, 256>>>(pts, out);
}